// round 1
// baseline (speedup 1.0000x reference)
#include <cuda_runtime.h>
#include <cuda_bf16.h>
#include <math.h>

// ---------------------------------------------------------------------------
// Fused 2-bit quantized CNN forward:
//   block(i): conv3x3(pad1, quantized weights) -> PACT quant_act -> maxpool2
//   then global max over HW, then 1x1 quantized conv -> [B,10]
// ---------------------------------------------------------------------------

// ---- static device scratch (no allocations allowed) -----------------------
__device__ float g_qw1[32 * 3 * 9];
__device__ float g_qw2[64 * 32 * 9];
__device__ float g_qw3[128 * 64 * 9];
__device__ float g_qwc[10 * 128];
__device__ float g_h1[32L * 32 * 112 * 112];   // 51.4 MB
__device__ float g_h2[32L * 64 * 56 * 56];     // 25.7 MB
__device__ float g_h3[32L * 128 * 28 * 28];    // 12.8 MB

// ---- weight fake-quant: s = max(|w|)/qmax (qmax=1 for 2 bits), q=round(w/s)*s
__global__ void quant_weight_kernel(const float* __restrict__ w,
                                    float* __restrict__ qw, int n) {
    __shared__ float red[32];
    float m = 0.f;
    for (int i = threadIdx.x; i < n; i += blockDim.x)
        m = fmaxf(m, fabsf(w[i]));
    #pragma unroll
    for (int o = 16; o; o >>= 1)
        m = fmaxf(m, __shfl_xor_sync(0xffffffffu, m, o));
    if ((threadIdx.x & 31) == 0) red[threadIdx.x >> 5] = m;
    __syncthreads();
    if (threadIdx.x < 32) {
        float v = red[threadIdx.x];
        #pragma unroll
        for (int o = 16; o; o >>= 1)
            v = fmaxf(v, __shfl_xor_sync(0xffffffffu, v, o));
        if (threadIdx.x == 0) red[0] = v;
    }
    __syncthreads();
    const float s = fmaxf(red[0], 1e-8f);
    for (int i = threadIdx.x; i < n; i += blockDim.x)
        qw[i] = rintf(w[i] / s) * s;   // rintf = round-half-even, matches jnp.round
}

// ---- fused conv3x3(pad1) + PACT quant_act + maxpool2 -----------------------
// 128 threads: 16x8 pooled tile; OCB output channels per block.
template <int IC, int OC, int H, int W, int OCB>
__global__ void conv_qact_pool(const float* __restrict__ x,
                               const float* __restrict__ qw,
                               const float* __restrict__ alpha_p,
                               float* __restrict__ out) {
    constexpr int PH = H / 2, PW = W / 2;
    constexpr int TPX = 16, TPY = 8;
    constexpr int TIX = 2 * TPX + 2;   // 34
    constexpr int TIY = 2 * TPY + 2;   // 18
    constexpr int TILES_Y = (PH + TPY - 1) / TPY;

    __shared__ float sx[TIY][TIX];
    __shared__ float sw[OCB][9];

    const int tid = threadIdx.x;          // 0..127
    const int tx = tid & 15;
    const int ty = tid >> 4;

    const int tile_x = blockIdx.x;
    const int tile_y = blockIdx.y % TILES_Y;
    const int b      = blockIdx.y / TILES_Y;
    const int oc0    = blockIdx.z * OCB;

    const int px0 = tile_x * TPX;
    const int py0 = tile_y * TPY;
    const int ix0 = 2 * px0 - 1;          // input origin incl. padding
    const int iy0 = 2 * py0 - 1;

    float acc[OCB][4];
    #pragma unroll
    for (int j = 0; j < OCB; j++)
        #pragma unroll
        for (int p = 0; p < 4; p++) acc[j][p] = 0.f;

    const float* xb = x + (long)b * IC * H * W;

    for (int ic = 0; ic < IC; ++ic) {
        __syncthreads();
        // load 18x34 input tile (zero-padded at borders)
        const float* xc = xb + (long)ic * H * W;
        #pragma unroll
        for (int i = tid; i < TIY * TIX; i += 128) {
            const int r = i / TIX, c = i % TIX;
            const int gy = iy0 + r, gx = ix0 + c;
            float v = 0.f;
            if (gy >= 0 && gy < H && gx >= 0 && gx < W) v = xc[gy * W + gx];
            sx[r][c] = v;
        }
        // load OCB*9 weights for this ic
        if (tid < OCB * 9) {
            const int j = tid / 9, t = tid % 9;
            sw[j][t] = qw[((oc0 + j) * IC + ic) * 9 + t];
        }
        __syncthreads();

        // 4x4 input window (covers 2x2 conv positions of a 3x3 kernel)
        float win[4][4];
        #pragma unroll
        for (int r = 0; r < 4; r++)
            #pragma unroll
            for (int c = 0; c < 4; c++)
                win[r][c] = sx[2 * ty + r][2 * tx + c];

        #pragma unroll
        for (int j = 0; j < OCB; j++) {
            float w[9];
            #pragma unroll
            for (int t = 0; t < 9; t++) w[t] = sw[j][t];
            #pragma unroll
            for (int p = 0; p < 4; p++) {
                const int dy = p >> 1, dx = p & 1;
                float a = acc[j][p];
                #pragma unroll
                for (int ky = 0; ky < 3; ky++)
                    #pragma unroll
                    for (int kx = 0; kx < 3; kx++)
                        a = fmaf(win[dy + ky][dx + kx], w[ky * 3 + kx], a);
                acc[j][p] = a;
            }
        }
    }

    // PACT quant_act (bits=2, shift=0): q = round(clip(y,0,a)*3/a)*a/3, then 2x2 max
    const float alpha = __ldg(alpha_p);
    const float scale = alpha * (1.f / 3.f);
    const float inv_scale = 3.f / alpha;

    const int px = px0 + tx, py = py0 + ty;
    if (px < PW && py < PH) {
        #pragma unroll
        for (int j = 0; j < OCB; j++) {
            float m = 0.f;  // quantized values are >= 0
            #pragma unroll
            for (int p = 0; p < 4; p++) {
                const float y = fminf(fmaxf(acc[j][p], 0.f), alpha);
                const float q = rintf(y * inv_scale) * scale;
                m = fmaxf(m, q);
            }
            out[(((long)b * OC + oc0 + j) * PH + py) * PW + px] = m;
        }
    }
}

// ---- global max over 28x28 + 1x1 quantized conv classifier -----------------
__global__ void gmax_fc_kernel(const float* __restrict__ h3,
                               const float* __restrict__ qwc,
                               float* __restrict__ out) {
    __shared__ float gmax[128];
    const int b = blockIdx.x;
    const int tid = threadIdx.x;          // 256 threads = 8 warps
    const int lane = tid & 31, warp = tid >> 5;
    const int HW = 28 * 28;

    for (int c = warp; c < 128; c += 8) {
        const float* p = h3 + ((long)b * 128 + c) * HW;
        float m = -INFINITY;
        for (int i = lane; i < HW; i += 32) m = fmaxf(m, p[i]);
        #pragma unroll
        for (int o = 16; o; o >>= 1)
            m = fmaxf(m, __shfl_xor_sync(0xffffffffu, m, o));
        if (lane == 0) gmax[c] = m;
    }
    __syncthreads();

    if (tid < 10) {
        float s = 0.f;
        #pragma unroll 8
        for (int c = 0; c < 128; c++)
            s = fmaf(gmax[c], qwc[tid * 128 + c], s);
        out[b * 10 + tid] = s;
    }
}

// ---------------------------------------------------------------------------
extern "C" void kernel_launch(void* const* d_in, const int* in_sizes, int n_in,
                              void* d_out, int out_size) {
    const float* x  = (const float*)d_in[0];
    const float* w1 = (const float*)d_in[1];
    const float* w2 = (const float*)d_in[2];
    const float* w3 = (const float*)d_in[3];
    const float* wc = (const float*)d_in[4];
    const float* a1 = (const float*)d_in[5];
    const float* a2 = (const float*)d_in[6];
    const float* a3 = (const float*)d_in[7];

    float *qw1, *qw2, *qw3, *qwc, *h1, *h2, *h3;
    cudaGetSymbolAddress((void**)&qw1, g_qw1);
    cudaGetSymbolAddress((void**)&qw2, g_qw2);
    cudaGetSymbolAddress((void**)&qw3, g_qw3);
    cudaGetSymbolAddress((void**)&qwc, g_qwc);
    cudaGetSymbolAddress((void**)&h1,  g_h1);
    cudaGetSymbolAddress((void**)&h2,  g_h2);
    cudaGetSymbolAddress((void**)&h3,  g_h3);

    // quantize all weight tensors (tiny)
    quant_weight_kernel<<<1, 1024>>>(w1, qw1, 32 * 3 * 9);
    quant_weight_kernel<<<1, 1024>>>(w2, qw2, 64 * 32 * 9);
    quant_weight_kernel<<<1, 1024>>>(w3, qw3, 128 * 64 * 9);
    quant_weight_kernel<<<1, 1024>>>(wc, qwc, 10 * 128);

    // block 1: [32,3,224,224] -> [32,32,112,112]
    conv_qact_pool<3, 32, 224, 224, 8>
        <<<dim3(7, 14 * 32, 32 / 8), 128>>>(x, qw1, a1, h1);
    // block 2: [32,32,112,112] -> [32,64,56,56]
    conv_qact_pool<32, 64, 112, 112, 8>
        <<<dim3(4, 7 * 32, 64 / 8), 128>>>(h1, qw2, a2, h2);
    // block 3: [32,64,56,56] -> [32,128,28,28]
    conv_qact_pool<64, 128, 56, 56, 8>
        <<<dim3(2, 4 * 32, 128 / 8), 128>>>(h2, qw3, a3, h3);

    // global max + classifier: [32,128,28,28] -> [32,10]
    gmax_fc_kernel<<<32, 256>>>(h3, qwc, (float*)d_out);
}

// round 2
// speedup vs baseline: 3.3322x; 3.3322x over previous
#include <cuda_runtime.h>
#include <cuda_bf16.h>
#include <stdint.h>
#include <math.h>

// ---------------------------------------------------------------------------
// 2-bit quantized CNN forward, int8/dp4a fast path.
//   After quant_act, activations are (alpha/3)*code, code in {0..3}.
//   Quantized weights are s*{-1,0,1}.  So conv2/conv3 are exact int8 GEMMs:
//   conv = (sum code*wint) * (alpha_prev/3 * s_w)  -> dp4a.
// Layouts: activations channel-last [B,H,W,C] int8 codes; weights packed
//   [OC][9][IC/4] int8x4.
// ---------------------------------------------------------------------------

// ---- static device scratch -------------------------------------------------
__device__ float   g_qw1[32 * 3 * 9];        // conv1 weights, fake-quant fp32
__device__ float   g_qwc[10 * 128];          // classifier weights, fp32
__device__ int     g_wp2[64 * 9 * 8];        // conv2 packed int8 weights
__device__ int     g_wp3[128 * 9 * 16];      // conv3 packed int8 weights
__device__ float   g_ws2[1];                 // conv2 weight scale
__device__ float   g_ws3[1];                 // conv3 weight scale
__device__ uint8_t g_c1[32L * 112 * 112 * 32];  // 12.8 MB codes
__device__ uint8_t g_c2[32L * 56 * 56 * 64];    //  6.4 MB codes
__device__ uint8_t g_c3[32L * 28 * 28 * 128];   //  3.2 MB codes

// ---- block-wide max-abs reduction helper ------------------------------------
__device__ __forceinline__ float block_maxabs(const float* __restrict__ w, int n,
                                              float* red /*smem[32]*/) {
    float m = 0.f;
    for (int i = threadIdx.x; i < n; i += blockDim.x)
        m = fmaxf(m, fabsf(w[i]));
    #pragma unroll
    for (int o = 16; o; o >>= 1)
        m = fmaxf(m, __shfl_xor_sync(0xffffffffu, m, o));
    if ((threadIdx.x & 31) == 0) red[threadIdx.x >> 5] = m;
    __syncthreads();
    if (threadIdx.x < 32) {
        float v = (threadIdx.x < (int)(blockDim.x >> 5)) ? red[threadIdx.x] : 0.f;
        #pragma unroll
        for (int o = 16; o; o >>= 1)
            v = fmaxf(v, __shfl_xor_sync(0xffffffffu, v, o));
        if (threadIdx.x == 0) red[0] = v;
    }
    __syncthreads();
    return fmaxf(red[0], 1e-8f);
}

// ---- fp fake-quant for conv1 / classifier weights ---------------------------
__global__ void quant_weight_kernel(const float* __restrict__ w,
                                    float* __restrict__ qw, int n) {
    __shared__ float red[32];
    const float s = block_maxabs(w, n, red);
    for (int i = threadIdx.x; i < n; i += blockDim.x)
        qw[i] = rintf(w[i] / s) * s;          // round-half-even = jnp.round
}

// ---- int8 quant + pack for dp4a convs:  w[OC][IC][3][3] -> [OC][9][IC/4] ----
template <int OC, int IC>
__global__ void quant_pack_kernel(const float* __restrict__ w,
                                  int* __restrict__ wpk,
                                  float* __restrict__ wscale) {
    __shared__ float red[32];
    const float s = block_maxabs(w, OC * IC * 9, red);
    if (threadIdx.x == 0) wscale[0] = s;
    constexpr int IC4 = IC / 4;
    const float inv_s = 1.f / s;
    for (int widx = threadIdx.x; widx < OC * 9 * IC4; widx += blockDim.x) {
        const int oc  = widx / (9 * IC4);
        const int r   = widx % (9 * IC4);
        const int t   = r / IC4;
        const int ic4 = r % IC4;
        uint32_t word = 0;
        #pragma unroll
        for (int l = 0; l < 4; l++) {
            const float wv = w[((oc * IC + ic4 * 4 + l) * 9) + t];
            const int   c  = (int)rintf(wv * inv_s);       // in {-1,0,1}
            word |= ((uint32_t)(uint8_t)(int8_t)c) << (8 * l);
        }
        wpk[widx] = (int)word;
    }
}

// ---- block 1: fp32 conv3x3(pad1) + quant_act + maxpool2 -> int8 codes -------
// 128 threads: 16x8 pooled tile, OCB=8 channels/block. Output [B,PH,PW,OC].
template <int IC, int OC, int H, int W, int OCB>
__global__ void conv_fp_qact_pool(const float* __restrict__ x,
                                  const float* __restrict__ qw,
                                  const float* __restrict__ alpha_p,
                                  uint8_t* __restrict__ out) {
    constexpr int PH = H / 2, PW = W / 2;
    constexpr int TPX = 16, TPY = 8;
    constexpr int TIX = 2 * TPX + 2, TIY = 2 * TPY + 2;   // 34 x 18
    constexpr int TILES_Y = (PH + TPY - 1) / TPY;

    __shared__ float sx[TIY][TIX];
    __shared__ float sw[OCB][9];

    const int tid = threadIdx.x;
    const int tx = tid & 15, ty = tid >> 4;
    const int tile_x = blockIdx.x;
    const int tile_y = blockIdx.y % TILES_Y;
    const int b      = blockIdx.y / TILES_Y;
    const int oc0    = blockIdx.z * OCB;

    const int px0 = tile_x * TPX, py0 = tile_y * TPY;
    const int ix0 = 2 * px0 - 1,  iy0 = 2 * py0 - 1;

    float acc[OCB][4];
    #pragma unroll
    for (int j = 0; j < OCB; j++)
        #pragma unroll
        for (int p = 0; p < 4; p++) acc[j][p] = 0.f;

    const float* xb = x + (long)b * IC * H * W;

    for (int ic = 0; ic < IC; ++ic) {
        __syncthreads();
        const float* xc = xb + (long)ic * H * W;
        for (int i = tid; i < TIY * TIX; i += 128) {
            const int r = i / TIX, c = i % TIX;
            const int gy = iy0 + r, gx = ix0 + c;
            float v = 0.f;
            if (gy >= 0 && gy < H && gx >= 0 && gx < W) v = xc[gy * W + gx];
            sx[r][c] = v;
        }
        if (tid < OCB * 9) {
            const int j = tid / 9, t = tid % 9;
            sw[j][t] = qw[((oc0 + j) * IC + ic) * 9 + t];
        }
        __syncthreads();

        float win[4][4];
        #pragma unroll
        for (int r = 0; r < 4; r++)
            #pragma unroll
            for (int c = 0; c < 4; c++)
                win[r][c] = sx[2 * ty + r][2 * tx + c];

        #pragma unroll
        for (int j = 0; j < OCB; j++) {
            float w[9];
            #pragma unroll
            for (int t = 0; t < 9; t++) w[t] = sw[j][t];
            #pragma unroll
            for (int p = 0; p < 4; p++) {
                const int dy = p >> 1, dx = p & 1;
                float a = acc[j][p];
                #pragma unroll
                for (int ky = 0; ky < 3; ky++)
                    #pragma unroll
                    for (int kx = 0; kx < 3; kx++)
                        a = fmaf(win[dy + ky][dx + kx], w[ky * 3 + kx], a);
                acc[j][p] = a;
            }
        }
    }

    // maxpool first (quant_act is monotone), then quantize once -> code 0..3
    const float alpha = __ldg(alpha_p);
    const float inv_scale = 3.f / alpha;
    const int px = px0 + tx, py = py0 + ty;
    if (px < PW && py < PH) {
        uint32_t lo = 0, hi = 0;
        #pragma unroll
        for (int j = 0; j < OCB; j++) {
            float m = fmaxf(fmaxf(acc[j][0], acc[j][1]),
                            fmaxf(acc[j][2], acc[j][3]));
            const float y = fminf(fmaxf(m, 0.f), alpha);
            const uint32_t code = (uint32_t)(int)rintf(y * inv_scale);
            if (j < 4) lo |= code << (8 * j);
            else       hi |= code << (8 * (j - 4));
        }
        uint2* dst = (uint2*)&out[(((long)b * PH + py) * PW + px) * OC + oc0];
        *dst = make_uint2(lo, hi);
    }
}

// ---- blocks 2/3: dp4a conv3x3(pad1) + quant_act + maxpool2 ------------------
// Input codes [B,H,W,IC] (as u32 words of 4 channels), packed int8 weights.
template <int IC, int OC, int H, int W, int OCB>
__global__ void conv_dp4a_qact_pool(const uint32_t* __restrict__ xin,
                                    const int* __restrict__ wpk,
                                    const float* __restrict__ wscale_p,
                                    const float* __restrict__ aprev_p,
                                    const float* __restrict__ acur_p,
                                    uint8_t* __restrict__ out) {
    constexpr int IC4 = IC / 4;
    constexpr int PH = H / 2, PW = W / 2;
    constexpr int TPX = 16, TPY = 8;
    constexpr int TIX = 2 * TPX + 2, TIY = 2 * TPY + 2;   // 34 x 18
    constexpr int TIXP = TIX + 1;                          // bank-stagger pad
    constexpr int TILES_Y = (PH + TPY - 1) / TPY;

    __shared__ uint32_t sx[IC4][TIY][TIXP];
    __shared__ int      sw[OCB][9][IC4];

    const int tid = threadIdx.x;
    const int tx = tid & 15, ty = tid >> 4;
    const int tile_x = blockIdx.x;
    const int tile_y = blockIdx.y % TILES_Y;
    const int b      = blockIdx.y / TILES_Y;
    const int oc0    = blockIdx.z * OCB;

    const int px0 = tile_x * TPX, py0 = tile_y * TPY;
    const int ix0 = 2 * px0 - 1,  iy0 = 2 * py0 - 1;

    // load all weights for this oc-group (whole IC range fits in smem)
    for (int i = tid; i < OCB * 9 * IC4; i += 128) {
        const int j = i / (9 * IC4), r = i % (9 * IC4);
        ((int*)sw)[j * 9 * IC4 + r] = wpk[(long)(oc0 + j) * 9 * IC4 + r];
    }
    // load input tile: flat over (pixel, ic4-word); consecutive tid ->
    // consecutive words of one pixel -> coalesced global reads
    for (int i = tid; i < TIY * TIX * IC4; i += 128) {
        const int k   = i % IC4;
        const int pix = i / IC4;
        const int r = pix / TIX, c = pix % TIX;
        const int gy = iy0 + r, gx = ix0 + c;
        uint32_t v = 0;
        if (gy >= 0 && gy < H && gx >= 0 && gx < W)
            v = xin[(((long)b * H + gy) * W + gx) * IC4 + k];
        sx[k][r][c] = v;
    }
    __syncthreads();

    int acc[OCB][4];
    #pragma unroll
    for (int j = 0; j < OCB; j++)
        #pragma unroll
        for (int p = 0; p < 4; p++) acc[j][p] = 0;

    #pragma unroll 1
    for (int k = 0; k < IC4; ++k) {
        uint32_t win[4][4];
        #pragma unroll
        for (int r = 0; r < 4; r++)
            #pragma unroll
            for (int c = 0; c < 4; c++)
                win[r][c] = sx[k][2 * ty + r][2 * tx + c];

        #pragma unroll
        for (int j = 0; j < OCB; j++) {
            int w[9];
            #pragma unroll
            for (int t = 0; t < 9; t++) w[t] = sw[j][t][k];
            #pragma unroll
            for (int p = 0; p < 4; p++) {
                const int dy = p >> 1, dx = p & 1;
                int a = acc[j][p];
                #pragma unroll
                for (int ky = 0; ky < 3; ky++)
                    #pragma unroll
                    for (int kx = 0; kx < 3; kx++)
                        a = __dp4a((int)win[dy + ky][dx + kx], w[ky * 3 + kx], a);
                acc[j][p] = a;
            }
        }
    }

    // combined scale > 0 -> int max commutes with scaling & quantization
    const float combined = (__ldg(aprev_p) * (1.f / 3.f)) * __ldg(wscale_p);
    const float alpha = __ldg(acur_p);
    const float inv_scale = 3.f / alpha;

    const int px = px0 + tx, py = py0 + ty;
    if (px < PW && py < PH) {
        uint32_t lo = 0, hi = 0;
        #pragma unroll
        for (int j = 0; j < OCB; j++) {
            const int mi = max(max(acc[j][0], acc[j][1]),
                               max(acc[j][2], acc[j][3]));
            const float v = (float)mi * combined;
            const float y = fminf(fmaxf(v, 0.f), alpha);
            const uint32_t code = (uint32_t)(int)rintf(y * inv_scale);
            if (j < 4) lo |= code << (8 * j);
            else       hi |= code << (8 * (j - 4));
        }
        uint2* dst = (uint2*)&out[(((long)b * PH + py) * PW + px) * OC + oc0];
        *dst = make_uint2(lo, hi);
    }
}

// ---- global max over 28x28 + 1x1 quantized conv classifier ------------------
__global__ void gmax_fc_kernel(const uint8_t* __restrict__ h3,
                               const float* __restrict__ qwc,
                               const float* __restrict__ a3_p,
                               float* __restrict__ out) {
    __shared__ float gm[128];
    const int b = blockIdx.x;
    const int c = threadIdx.x;   // 128 threads, one channel each
    int m = 0;
    const uint8_t* p = h3 + (long)b * 784 * 128 + c;
    for (int i = 0; i < 784; i++)
        m = max(m, (int)p[(long)i * 128]);
    gm[c] = (float)m * (__ldg(a3_p) * (1.f / 3.f));
    __syncthreads();
    if (c < 10) {
        float s = 0.f;
        #pragma unroll 8
        for (int k = 0; k < 128; k++)
            s = fmaf(gm[k], qwc[c * 128 + k], s);
        out[b * 10 + c] = s;
    }
}

// ---------------------------------------------------------------------------
extern "C" void kernel_launch(void* const* d_in, const int* in_sizes, int n_in,
                              void* d_out, int out_size) {
    const float* x  = (const float*)d_in[0];
    const float* w1 = (const float*)d_in[1];
    const float* w2 = (const float*)d_in[2];
    const float* w3 = (const float*)d_in[3];
    const float* wc = (const float*)d_in[4];
    const float* a1 = (const float*)d_in[5];
    const float* a2 = (const float*)d_in[6];
    const float* a3 = (const float*)d_in[7];

    float *qw1, *qwc, *ws2, *ws3;
    int *wp2, *wp3;
    uint8_t *c1, *c2, *c3;
    cudaGetSymbolAddress((void**)&qw1, g_qw1);
    cudaGetSymbolAddress((void**)&qwc, g_qwc);
    cudaGetSymbolAddress((void**)&wp2, g_wp2);
    cudaGetSymbolAddress((void**)&wp3, g_wp3);
    cudaGetSymbolAddress((void**)&ws2, g_ws2);
    cudaGetSymbolAddress((void**)&ws3, g_ws3);
    cudaGetSymbolAddress((void**)&c1,  g_c1);
    cudaGetSymbolAddress((void**)&c2,  g_c2);
    cudaGetSymbolAddress((void**)&c3,  g_c3);

    quant_weight_kernel<<<1, 1024>>>(w1, qw1, 32 * 3 * 9);
    quant_weight_kernel<<<1, 1024>>>(wc, qwc, 10 * 128);
    quant_pack_kernel<64, 32><<<1, 1024>>>(w2, wp2, ws2);
    quant_pack_kernel<128, 64><<<1, 1024>>>(w3, wp3, ws3);

    // block 1 (fp32): [32,3,224,224] -> codes [32,112,112,32]
    conv_fp_qact_pool<3, 32, 224, 224, 8>
        <<<dim3(7, 14 * 32, 4), 128>>>(x, qw1, a1, c1);
    // block 2 (dp4a): -> codes [32,56,56,64]
    conv_dp4a_qact_pool<32, 64, 112, 112, 8>
        <<<dim3(4, 7 * 32, 8), 128>>>((const uint32_t*)c1, wp2, ws2, a1, a2, c2);
    // block 3 (dp4a): -> codes [32,28,28,128]
    conv_dp4a_qact_pool<64, 128, 56, 56, 8>
        <<<dim3(2, 4 * 32, 16), 128>>>((const uint32_t*)c2, wp3, ws3, a2, a3, c3);

    // global max + classifier
    gmax_fc_kernel<<<32, 128>>>(c3, qwc, a3, (float*)d_out);
}

// round 3
// speedup vs baseline: 3.8280x; 1.1488x over previous
#include <cuda_runtime.h>
#include <cuda_bf16.h>
#include <stdint.h>
#include <math.h>

// ---------------------------------------------------------------------------
// 2-bit quantized CNN forward.
//  conv1: fp32 scalar (IC=3) -> codes
//  conv2/conv3: int8 implicit-GEMM via mma.sync.m16n8k32.s8 (IMMA),
//    exact integer math: conv = (sum code*wint) * (alpha_prev/3 * s_w).
//  Activations channel-last [B,H,W,C] u8 codes {0..3}; weights pre-packed
//  into IMMA B-fragment register layout.
// ---------------------------------------------------------------------------

__device__ unsigned g_smax[4];                 // maxabs bits: w1, wc, w2, w3
__device__ float    g_qw1[32 * 3 * 9];
__device__ float    g_qwc[10 * 128];
__device__ int      g_wf2[9 * 64 * 8];         // [tap][oc][p]  B-frag words
__device__ int      g_wf3[9 * 2 * 128 * 8];    // [tap][chunk][oc][p]
__device__ uint8_t  g_c1[32L * 112 * 112 * 32];
__device__ uint8_t  g_c2[32L * 56 * 56 * 64];
__device__ uint8_t  g_c3[32L * 28 * 28 * 128];

// ---- helpers ---------------------------------------------------------------
__device__ __forceinline__ uint32_t smem_u32(const void* p) {
    uint32_t a;
    asm("{ .reg .u64 t; cvta.to.shared.u64 t, %1; cvt.u32.u64 %0, t; }"
        : "=r"(a) : "l"(p));
    return a;
}

__device__ __forceinline__ void ldsm4(uint32_t addr, int& a0, int& a1,
                                      int& a2, int& a3) {
    asm volatile("ldmatrix.sync.aligned.m8n8.x4.shared.b16 {%0,%1,%2,%3},[%4];"
                 : "=r"(a0), "=r"(a1), "=r"(a2), "=r"(a3) : "r"(addr));
}

__device__ __forceinline__ void mma_s8(int* d, int a0, int a1, int a2, int a3,
                                       int b0, int b1) {
    asm("mma.sync.aligned.m16n8k32.row.col.s32.s8.s8.s32 "
        "{%0,%1,%2,%3},{%4,%5,%6,%7},{%8,%9},{%0,%1,%2,%3};"
        : "+r"(d[0]), "+r"(d[1]), "+r"(d[2]), "+r"(d[3])
        : "r"(a0), "r"(a1), "r"(a2), "r"(a3), "r"(b0), "r"(b1));
}

__device__ __forceinline__ float get_scale(int t) {
    return fmaxf(__uint_as_float(g_smax[t]), 1e-8f);
}

// ---- prologue 1: max|w| for the 4 weight tensors (multi-block) --------------
__global__ void maxabs_kernel(const float* __restrict__ w1,
                              const float* __restrict__ wc,
                              const float* __restrict__ w2,
                              const float* __restrict__ w3) {
    __shared__ float red[8];
    const int blk = blockIdx.x;
    int t, base, cnt;
    const float* p;
    if (blk == 0)      { t = 0; p = w1; base = 0; cnt = 864; }
    else if (blk == 1) { t = 1; p = wc; base = 0; cnt = 1280; }
    else if (blk < 6)  { t = 2; p = w2; base = (blk - 2) * 4608; cnt = 4608; }
    else               { t = 3; p = w3; base = (blk - 6) * 4608; cnt = 4608; }
    float m = 0.f;
    for (int i = threadIdx.x; i < cnt; i += 256)
        m = fmaxf(m, fabsf(p[base + i]));
    #pragma unroll
    for (int o = 16; o; o >>= 1)
        m = fmaxf(m, __shfl_xor_sync(0xffffffffu, m, o));
    if ((threadIdx.x & 31) == 0) red[threadIdx.x >> 5] = m;
    __syncthreads();
    if (threadIdx.x == 0) {
        float v = red[0];
        #pragma unroll
        for (int i = 1; i < 8; i++) v = fmaxf(v, red[i]);
        atomicMax(&g_smax[t], __float_as_uint(v));  // |w|>=0 -> bit-monotone
    }
}

// ---- prologue 2: quantize + pack all weight tensors -------------------------
// B-fragment layout: word p (0..7) of [tap][(chunk)][oc]:
//   icw = (p>>1) + (p&1)*4  (so LDS.64 at p=2*(lane&3) yields (b0,b1))
__global__ void pack_kernel(const float* __restrict__ w1,
                            const float* __restrict__ wc,
                            const float* __restrict__ w2,
                            const float* __restrict__ w3) {
    const int blk = blockIdx.x;
    if (blk == 0) {
        const float s = get_scale(0);
        for (int i = threadIdx.x; i < 864; i += 256)
            g_qw1[i] = rintf(w1[i] / s) * s;
    } else if (blk == 1) {
        const float s = get_scale(1);
        for (int i = threadIdx.x; i < 1280; i += 256)
            g_qwc[i] = rintf(wc[i] / s) * s;
    } else if (blk == 2) {
        const float inv_s = 1.f / get_scale(2);
        for (int i = threadIdx.x; i < 9 * 64 * 8; i += 256) {
            const int tap = i / 512, r = i % 512, oc = r >> 3, p = r & 7;
            const int icw = (p >> 1) + ((p & 1) << 2);
            uint32_t word = 0;
            #pragma unroll
            for (int l = 0; l < 4; l++) {
                const int ic = icw * 4 + l;
                const int c = (int)rintf(w2[(oc * 32 + ic) * 9 + tap] * inv_s);
                word |= ((uint32_t)(uint8_t)(int8_t)c) << (8 * l);
            }
            g_wf2[i] = (int)word;
        }
    } else {
        const float inv_s = 1.f / get_scale(3);
        for (int i = threadIdx.x; i < 9 * 2 * 128 * 8; i += 256) {
            const int tap = i / 2048, r = i % 2048;
            const int chunk = r >> 10, r2 = r & 1023, oc = r2 >> 3, p = r2 & 7;
            const int icw = (p >> 1) + ((p & 1) << 2);
            uint32_t word = 0;
            #pragma unroll
            for (int l = 0; l < 4; l++) {
                const int ic = chunk * 32 + icw * 4 + l;
                const int c = (int)rintf(w3[(oc * 64 + ic) * 9 + tap] * inv_s);
                word |= ((uint32_t)(uint8_t)(int8_t)c) << (8 * l);
            }
            g_wf3[i] = (int)word;
        }
    }
}

// ---- block 1: fp32 conv3x3(pad1) + quant_act + maxpool2 -> codes ------------
// 128 threads, 16x8 pooled tile, OCB=8, single __syncthreads.
__global__ __launch_bounds__(128) void conv1_kernel(
    const float* __restrict__ x, const float* __restrict__ alpha_p,
    uint8_t* __restrict__ out) {
    constexpr int H = 224, W = 224, PH = 112, PW = 112, OC = 32, OCB = 8;
    __shared__ float sx[3][18][34];
    __shared__ float sw[OCB][3][9];

    const int tid = threadIdx.x;
    const int tx = tid & 15, ty = tid >> 4;
    const int tile_x = blockIdx.x;
    const int tile_y = blockIdx.y % 14;
    const int b      = blockIdx.y / 14;
    const int oc0    = blockIdx.z * OCB;

    const int px0 = tile_x * 16, py0 = tile_y * 8;
    const int ix0 = 2 * px0 - 1, iy0 = 2 * py0 - 1;

    const float* xb = x + (long)b * 3 * H * W;
    for (int i = tid; i < 3 * 18 * 34; i += 128) {
        const int ic = i / 612, rr = (i % 612) / 34, cc = i % 34;
        const int gy = iy0 + rr, gx = ix0 + cc;
        float v = 0.f;
        if (gy >= 0 && gy < H && gx >= 0 && gx < W)
            v = xb[(long)ic * H * W + gy * W + gx];
        sx[ic][rr][cc] = v;
    }
    if (tid < OCB * 27) {
        const int j = tid / 27, r27 = tid % 27;
        sw[j][r27 / 9][r27 % 9] = g_qw1[((oc0 + j) * 3 + r27 / 9) * 9 + r27 % 9];
    }
    __syncthreads();

    float acc[OCB][4];
    #pragma unroll
    for (int j = 0; j < OCB; j++)
        #pragma unroll
        for (int p = 0; p < 4; p++) acc[j][p] = 0.f;

    #pragma unroll
    for (int ic = 0; ic < 3; ic++) {
        float win[4][4];
        #pragma unroll
        for (int r = 0; r < 4; r++)
            #pragma unroll
            for (int c = 0; c < 4; c++)
                win[r][c] = sx[ic][2 * ty + r][2 * tx + c];
        #pragma unroll
        for (int j = 0; j < OCB; j++) {
            float w[9];
            #pragma unroll
            for (int t = 0; t < 9; t++) w[t] = sw[j][ic][t];
            #pragma unroll
            for (int p = 0; p < 4; p++) {
                const int dy = p >> 1, dx = p & 1;
                float a = acc[j][p];
                #pragma unroll
                for (int ky = 0; ky < 3; ky++)
                    #pragma unroll
                    for (int kx = 0; kx < 3; kx++)
                        a = fmaf(win[dy + ky][dx + kx], w[ky * 3 + kx], a);
                acc[j][p] = a;
            }
        }
    }

    const float alpha = __ldg(alpha_p);
    const float inv_scale = 3.f / alpha;
    const int px = px0 + tx, py = py0 + ty;
    uint32_t lo = 0, hi = 0;
    #pragma unroll
    for (int j = 0; j < OCB; j++) {
        const float m = fmaxf(fmaxf(acc[j][0], acc[j][1]),
                              fmaxf(acc[j][2], acc[j][3]));
        const float y = fminf(fmaxf(m, 0.f), alpha);
        const uint32_t code = (uint32_t)(int)rintf(y * inv_scale);
        if (j < 4) lo |= code << (8 * j);
        else       hi |= code << (8 * (j - 4));
    }
    *(uint2*)&out[(((long)b * PH + py) * PW + px) * OC + oc0] = make_uint2(lo, hi);
}

// ---- blocks 2/3: IMMA implicit-GEMM conv + quant_act + maxpool2 -------------
// Warp tile = 16 conv positions (8 wide x 2 tall) x NOC output channels.
// A: ldmatrix from channel-last smem tile (pixel stride PSTRIDE, padded for
// conflict-free phases). B: pre-packed fragment words, one LDS.64 each.
template <int H, int IC, int OC, int NOC, int TW, int TH, int WARPS, int PSTRIDE>
__global__ void conv_mma_qact_pool(const uint8_t* __restrict__ xin,
                                   const int* __restrict__ wf,
                                   const float* __restrict__ wscale_bits_unused,
                                   const float* __restrict__ aprev_p,
                                   const float* __restrict__ acur_p,
                                   int wtensor,      // g_smax index for weights
                                   uint8_t* __restrict__ out) {
    constexpr int CH  = IC / 32;           // k-chunks per tap
    constexpr int TIW = TW + 2, TIH = TH + 2;
    constexpr int OCG = NOC / 8;
    constexpr int VPP = IC / 16;           // uint4 per pixel
    constexpr int WTX = TW / 8, WTY = TH / 2, NWT = WTX * WTY;
    constexpr int Wd = H, PHW = H / 2;

    extern __shared__ __align__(16) uint8_t dsm[];
    uint8_t* stile = dsm;                                    // TIH*TIW*PSTRIDE
    int* swf = (int*)(dsm + TIH * TIW * PSTRIDE);            // 9*CH*NOC*8

    const int tid = threadIdx.x;
    const int tilesY = H / TH;
    const int by = blockIdx.y % tilesY;
    const int b  = blockIdx.y / tilesY;
    const int cx0 = blockIdx.x * TW, cy0 = by * TH;
    const int oc0 = blockIdx.z * NOC;

    for (int i = tid; i < 9 * CH * NOC * 8; i += blockDim.x) {
        const int p = i & 7, j = (i >> 3) % NOC, tc = (i >> 3) / NOC;
        swf[i] = wf[((tc * OC) + oc0 + j) * 8 + p];
    }
    for (int i = tid; i < TIH * TIW * VPP; i += blockDim.x) {
        const int v = i % VPP, pix = i / VPP;
        const int gx = cx0 - 1 + pix % TIW;
        const int gy = cy0 - 1 + pix / TIW;
        uint4 val = make_uint4(0, 0, 0, 0);
        if (gx >= 0 && gx < Wd && gy >= 0 && gy < H)
            val = *(const uint4*)(xin + (((long)b * H + gy) * Wd + gx) * IC + v * 16);
        *(uint4*)(stile + pix * PSTRIDE + v * 16) = val;
    }
    __syncthreads();

    const int warp = tid >> 5, lane = tid & 31;
    const uint32_t sbase = smem_u32(stile);
    const float combined = (__ldg(aprev_p) * (1.f / 3.f)) * get_scale(wtensor);
    const float alpha = __ldg(acur_p);
    const float inv_scale = 3.f / alpha;
    const int r = lane >> 2;

    for (int wt = warp; wt < NWT; wt += WARPS) {
        const int tx = wt % WTX, ty = wt / WTX;
        // ldmatrix per-lane row address: m0/m1 = position rows 0-7 / 8-15,
        // m2/m3 = same rows, k-bytes +16.
        const int piy = ty * 2 + ((lane >> 3) & 1);
        const int pix = tx * 8 + (lane & 7);
        const uint32_t abase = sbase + (piy * TIW + pix) * PSTRIDE
                             + ((lane >> 4) << 4);

        int acc[OCG][4];
        #pragma unroll
        for (int g = 0; g < OCG; g++)
            #pragma unroll
            for (int q = 0; q < 4; q++) acc[g][q] = 0;

        #pragma unroll
        for (int t = 0; t < 9; t++) {
            const int dy = t / 3, dx = t % 3;
            #pragma unroll
            for (int c = 0; c < CH; c++) {
                int a0, a1, a2, a3;
                ldsm4(abase + (dy * TIW + dx) * PSTRIDE + c * 32, a0, a1, a2, a3);
                #pragma unroll
                for (int g = 0; g < OCG; g++) {
                    const uint2 bb = *(const uint2*)
                        &swf[(((t * CH + c) * NOC) + g * 8 + (lane >> 2)) * 8
                             + 2 * (lane & 3)];
                    mma_s8(acc[g], a0, a1, a2, a3, (int)bb.x, (int)bb.y);
                }
            }
        }

        // epilogue: 2x2 maxpool in registers, quantize, pack 2 channels
        #pragma unroll
        for (int g = 0; g < OCG; g++) {
            const int v0 = max(acc[g][0], acc[g][2]);   // rows r, r+8 (vert)
            const int v1 = max(acc[g][1], acc[g][3]);
            const int o0 = max(v0, __shfl_xor_sync(0xffffffffu, v0, 4));
            const int o1 = max(v1, __shfl_xor_sync(0xffffffffu, v1, 4));
            if (!(r & 1)) {
                const int ppx = (cx0 >> 1) + tx * 4 + (r >> 1);
                const int ppy = (cy0 >> 1) + ty;
                const float f0 = fminf(fmaxf((float)o0 * combined, 0.f), alpha);
                const float f1 = fminf(fmaxf((float)o1 * combined, 0.f), alpha);
                const uint32_t c0 = (uint32_t)(int)rintf(f0 * inv_scale);
                const uint32_t c1 = (uint32_t)(int)rintf(f1 * inv_scale);
                const int oc = oc0 + g * 8 + (lane & 3) * 2;
                *(uint16_t*)(out + (((long)b * PHW + ppy) * PHW + ppx) * OC + oc)
                    = (uint16_t)(c0 | (c1 << 8));
            }
        }
    }
}

// ---- global max over 28x28 + 1x1 quantized conv classifier ------------------
__global__ void gmax_fc_kernel(const uint8_t* __restrict__ h3,
                               const float* __restrict__ a3_p,
                               float* __restrict__ out) {
    __shared__ float gm[128];
    const int b = blockIdx.x;
    const int c = threadIdx.x;
    int m = 0;
    const uint8_t* p = h3 + (long)b * 784 * 128 + c;
    for (int i = 0; i < 784; i++)
        m = max(m, (int)p[(long)i * 128]);
    gm[c] = (float)m * (__ldg(a3_p) * (1.f / 3.f));
    __syncthreads();
    if (c < 10) {
        float s = 0.f;
        #pragma unroll 8
        for (int k = 0; k < 128; k++)
            s = fmaf(gm[k], g_qwc[c * 128 + k], s);
        out[b * 10 + c] = s;
    }
}

// ---------------------------------------------------------------------------
extern "C" void kernel_launch(void* const* d_in, const int* in_sizes, int n_in,
                              void* d_out, int out_size) {
    const float* x  = (const float*)d_in[0];
    const float* w1 = (const float*)d_in[1];
    const float* w2 = (const float*)d_in[2];
    const float* w3 = (const float*)d_in[3];
    const float* wc = (const float*)d_in[4];
    const float* a1 = (const float*)d_in[5];
    const float* a2 = (const float*)d_in[6];
    const float* a3 = (const float*)d_in[7];

    int *wf2, *wf3;
    uint8_t *c1, *c2, *c3;
    cudaGetSymbolAddress((void**)&wf2, g_wf2);
    cudaGetSymbolAddress((void**)&wf3, g_wf3);
    cudaGetSymbolAddress((void**)&c1, g_c1);
    cudaGetSymbolAddress((void**)&c2, g_c2);
    cudaGetSymbolAddress((void**)&c3, g_c3);

    // conv2: IC=32, OC=64, conv grid 112x112, CTA tile 16x16, 8 warps
    auto k2 = conv_mma_qact_pool<112, 32, 64, 64, 16, 16, 8, 48>;
    constexpr int SM2 = 18 * 18 * 48 + 9 * 1 * 64 * 8 * 4;   // 33984
    // conv3: IC=64, OC=128 (32/CTA), conv grid 56x56, CTA tile 56x8, 7 warps
    auto k3 = conv_mma_qact_pool<56, 64, 128, 32, 56, 8, 7, 80>;
    constexpr int SM3 = 58 * 10 * 80 + 9 * 2 * 32 * 8 * 4;   // 64832
    cudaFuncSetAttribute(k2, cudaFuncAttributeMaxDynamicSharedMemorySize, SM2);
    cudaFuncSetAttribute(k3, cudaFuncAttributeMaxDynamicSharedMemorySize, SM3);

    maxabs_kernel<<<22, 256>>>(w1, wc, w2, w3);
    pack_kernel<<<4, 256>>>(w1, wc, w2, w3);

    // block 1: [32,3,224,224] -> codes [32,112,112,32]
    conv1_kernel<<<dim3(7, 14 * 32, 4), 128>>>(x, a1, c1);
    // block 2: -> codes [32,56,56,64]
    k2<<<dim3(7, 7 * 32, 1), 256, SM2>>>(c1, wf2, nullptr, a1, a2, 2, c2);
    // block 3: -> codes [32,28,28,128]
    k3<<<dim3(1, 7 * 32, 4), 224, SM3>>>(c2, wf3, nullptr, a2, a3, 3, c3);

    // global max + classifier
    gmax_fc_kernel<<<32, 128>>>(c3, a3, (float*)d_out);
}